// round 15
// baseline (speedup 1.0000x reference)
#include <cuda_runtime.h>
#include <cuda_bf16.h>
#include <stdint.h>

typedef unsigned long long ull;

// Problem dims
#define BDIM 32
#define TDIM 512
#define IDIM 512
#define HDIM 1024

// ---------------- scratch (static device globals; no allocation) ----------------
__device__ float g_xs[(size_t)TDIM * 8 * IDIM * 4];   // x staged: [t][grp][k][4b]
__device__ float g_hp1[8][4][HDIM * 4];               // h1 ring: [grp][slot][k][4b]
__device__ float g_hp2[8][4][HDIM * 4];               // h2 ring

__device__ unsigned g_fh1[1024];                      // [grp][cb] layer-0 progress
__device__ unsigned g_fh2[1024];                      // layer-1 progress

// ---------------- f32x2 helpers ----------------
__device__ __forceinline__ void ffma2(ull& d, ull a, ull b) {
    asm("fma.rn.f32x2 %0, %1, %2, %0;" : "+l"(d) : "l"(a), "l"(b));
}
__device__ __forceinline__ void add2(ull& d, ull a) {
    asm("add.rn.f32x2 %0, %0, %1;" : "+l"(d) : "l"(a));
}
__device__ __forceinline__ ull splat2(float x) {
    ull r;
    asm("mov.b64 %0, {%1, %1};" : "=l"(r) : "f"(x));
    return r;
}
__device__ __forceinline__ float2 unpack2(ull v) {
    float lo, hi;
    asm("mov.b64 {%0, %1}, %2;" : "=f"(lo), "=f"(hi) : "l"(v));
    return make_float2(lo, hi);
}
__device__ __forceinline__ float4 ldcg_f4(const void* p) {
    float4 v;
    asm volatile("ld.global.cg.v4.f32 {%0,%1,%2,%3}, [%4];"
                 : "=f"(v.x), "=f"(v.y), "=f"(v.z), "=f"(v.w) : "l"(p));
    return v;
}

// ---------------- stage x (+ flag init in CTA 0) ----------------
__global__ __launch_bounds__(256) void stage_x(const float* __restrict__ x) {
    int t = blockIdx.x;
    int tid = threadIdx.x;
    if (blockIdx.x == 0) {
        for (int i = tid; i < 1024; i += 256) {
            g_fh1[i] = 0;
            g_fh2[i] = 0;
        }
    }
    for (int idx = tid; idx < 8 * IDIM; idx += 256) {
        int sg = idx >> 9;
        int k  = idx & 511;
        const float* xb = x + (size_t)t * IDIM + k;
        float4 v;
        v.x = xb[(size_t)(sg * 4 + 0) * TDIM * IDIM];
        v.y = xb[(size_t)(sg * 4 + 1) * TDIM * IDIM];
        v.z = xb[(size_t)(sg * 4 + 2) * TDIM * IDIM];
        v.w = xb[(size_t)(sg * 4 + 3) * TDIM * IDIM];
        *(float4*)(g_xs + (((size_t)t * 8 + sg) << 11) + k * 4) = v;
    }
}

// ---------------- acc structure and helpers ----------------
struct Accs { ull v[16]; };   // [A0 b0..3 | A1 b0..3 | B0 b0..3 | B1 b0..3]

__device__ __forceinline__ void zero_accs(Accs& a) {
    #pragma unroll
    for (int i = 0; i < 16; i++) a.v[i] = 0ull;
}

__device__ __forceinline__ void acc_step(Accs& a, ulonglong2 w1, ulonglong2 w2,
                                         float4 h) {
    ull s0 = splat2(h.x), s1 = splat2(h.y);
    ull s2 = splat2(h.z), s3 = splat2(h.w);
    ffma2(a.v[0],  s0, w1.x); ffma2(a.v[4],  s0, w1.y);
    ffma2(a.v[8],  s0, w2.x); ffma2(a.v[12], s0, w2.y);
    ffma2(a.v[1],  s1, w1.x); ffma2(a.v[5],  s1, w1.y);
    ffma2(a.v[9],  s1, w2.x); ffma2(a.v[13], s1, w2.y);
    ffma2(a.v[2],  s2, w1.x); ffma2(a.v[6],  s2, w1.y);
    ffma2(a.v[10], s2, w2.x); ffma2(a.v[14], s2, w2.y);
    ffma2(a.v[3],  s3, w1.x); ffma2(a.v[7],  s3, w1.y);
    ffma2(a.v[11], s3, w2.x); ffma2(a.v[15], s3, w2.y);
}

// single-weight dot over CHUNKS*4*32 k
template<int CHUNKS>
__device__ __forceinline__ void dot_into(Accs& ac,
                                         const char* __restrict__ wA,
                                         const char* __restrict__ wB,
                                         const char* __restrict__ hbase) {
    float4 hbuf[2][4];
    #pragma unroll
    for (int j = 0; j < 4; j++)
        hbuf[0][j] = ldcg_f4(hbase + j * 512);
    #pragma unroll
    for (int c = 0; c < CHUNKS; c++) {
        if (c < CHUNKS - 1) {
            #pragma unroll
            for (int j = 0; j < 4; j++)
                hbuf[(c + 1) & 1][j] = ldcg_f4(hbase + ((c + 1) * 4 + j) * 512);
        }
        #pragma unroll
        for (int j = 0; j < 4; j++) {
            int koff = (c * 4 + j) * 1024;
            ulonglong2 w1 = *(const ulonglong2*)(wA + koff);
            ulonglong2 w2 = *(const ulonglong2*)(wB + koff);
            acc_step(ac, w1, w2, hbuf[c & 1][j]);
        }
    }
}

// dual-weight dot: read h once, accumulate into two acc sets
template<int CHUNKS>
__device__ __forceinline__ void dual_dot_into(Accs& xa, Accs& za,
                                              const char* __restrict__ waA,
                                              const char* __restrict__ waB,
                                              const char* __restrict__ wzA,
                                              const char* __restrict__ wzB,
                                              const char* __restrict__ hbase) {
    float4 hbuf[2][4];
    #pragma unroll
    for (int j = 0; j < 4; j++)
        hbuf[0][j] = ldcg_f4(hbase + j * 512);
    #pragma unroll
    for (int c = 0; c < CHUNKS; c++) {
        if (c < CHUNKS - 1) {
            #pragma unroll
            for (int j = 0; j < 4; j++)
                hbuf[(c + 1) & 1][j] = ldcg_f4(hbase + ((c + 1) * 4 + j) * 512);
        }
        #pragma unroll
        for (int j = 0; j < 4; j++) {
            int koff = (c * 4 + j) * 1024;
            float4 h = hbuf[c & 1][j];
            ulonglong2 w1 = *(const ulonglong2*)(waA + koff);
            ulonglong2 w2 = *(const ulonglong2*)(waB + koff);
            acc_step(xa, w1, w2, h);
            ulonglong2 z1 = *(const ulonglong2*)(wzA + koff);
            ulonglong2 z2 = *(const ulonglong2*)(wzB + koff);
            acc_step(za, z1, z2, h);
        }
    }
}

// butterfly reduction of 16 acc-pairs across 32 lanes -> 1 pair per lane
__device__ __forceinline__ ull reduce16(ull* a, int lane) {
    #pragma unroll
    for (int i = 0; i < 16; i++) {
        ull r = __shfl_xor_sync(0xffffffffu, a[i], 16);
        add2(a[i], r);
    }
    {
        int bit = lane & 1;
        #pragma unroll
        for (int i = 0; i < 8; i++) {
            ull snd = bit ? a[i] : a[i + 8];
            ull rcv = __shfl_xor_sync(0xffffffffu, snd, 1);
            a[i] = bit ? a[i + 8] : a[i];
            add2(a[i], rcv);
        }
    }
    {
        int bit = (lane >> 1) & 1;
        #pragma unroll
        for (int i = 0; i < 4; i++) {
            ull snd = bit ? a[i] : a[i + 4];
            ull rcv = __shfl_xor_sync(0xffffffffu, snd, 2);
            a[i] = bit ? a[i + 4] : a[i];
            add2(a[i], rcv);
        }
    }
    {
        int bit = (lane >> 2) & 1;
        #pragma unroll
        for (int i = 0; i < 2; i++) {
            ull snd = bit ? a[i] : a[i + 2];
            ull rcv = __shfl_xor_sync(0xffffffffu, snd, 4);
            a[i] = bit ? a[i + 2] : a[i];
            add2(a[i], rcv);
        }
    }
    {
        int bit = (lane >> 3) & 1;
        ull snd = bit ? a[0] : a[1];
        ull rcv = __shfl_xor_sync(0xffffffffu, snd, 8);
        a[0] = bit ? a[1] : a[0];
        add2(a[0], rcv);
    }
    return a[0];
}

__device__ __forceinline__ ull norm_reduce(const Accs& ac, int lane, int half) {
    ull a[16];
    if (half == 0) {
        #pragma unroll
        for (int i = 0; i < 16; i++) a[i] = ac.v[i];
    } else {
        #pragma unroll
        for (int i = 0; i < 8; i++) {
            a[i]     = ac.v[i + 8];
            a[i + 8] = ac.v[i];
        }
    }
    return reduce16(a, lane);
}

// poll all 128 flags of a group until min >= tt; returns the observed min
__device__ __forceinline__ unsigned poll_min(const unsigned* __restrict__ fpp,
                                             unsigned tt, int lane) {
    unsigned m;
    for (;;) {
        unsigned f0, f1, f2, f3;
        asm volatile("ld.acquire.gpu.u32 %0, [%1];" : "=r"(f0) : "l"(fpp + lane));
        asm volatile("ld.acquire.gpu.u32 %0, [%1];" : "=r"(f1) : "l"(fpp + lane + 32));
        asm volatile("ld.acquire.gpu.u32 %0, [%1];" : "=r"(f2) : "l"(fpp + lane + 64));
        asm volatile("ld.acquire.gpu.u32 %0, [%1];" : "=r"(f3) : "l"(fpp + lane + 96));
        unsigned mn = min(min(f0, f1), min(f2, f3));
        m = __reduce_min_sync(0xffffffffu, mn);
        if (m >= tt) break;
    }
    return m;
}

// 2-warp (same group, both k-halves) rendezvous via named barrier sg+1
__device__ __forceinline__ void barrier_pair(int sg) {
    asm volatile("bar.sync %0, 64;" :: "r"(sg + 1) : "memory");
}

// ---------------- k-split fused kernel ----------------
// 128 CTAs x 512 threads (16 warps). Warp (sg = wid&7, kh = wid>>3) handles
// batch group sg over k-half kh. Per iter: x-dot half -> polls -> dual-dot
// half (h1) -> reduce -> combine halves (smem + bar) -> kh0 finalizes A ->
// h2-dot half -> reduce -> combine -> kh0 finalizes B. Traffic-neutral
// split: each warp reads only its k-half of h. 2 named bars/iter.
#define WEIGHT_FLOATS (3 * 8 * HDIM + 8 * IDIM)
#define FU_SMEM_BYTES (WEIGHT_FLOATS * 4 + 2048)

__global__ __launch_bounds__(512, 1) void recur_fused(
    const float* __restrict__ xs,
    const float* __restrict__ Whh0,
    const float* __restrict__ Wih0,
    const float* __restrict__ Wih1,
    const float* __restrict__ Whh1,
    const float* __restrict__ bih0,
    const float* __restrict__ bhh0,
    const float* __restrict__ bih1,
    const float* __restrict__ bhh1,
    float* __restrict__ out)
{
    extern __shared__ __align__(16) float sm[];
    float* Wh0 = sm;                       // [k][8c], k<1024
    float* Wi1 = sm + 8 * HDIM;
    float* Wh1 = sm + 16 * HDIM;
    float* Wi0 = sm + 24 * HDIM;           // [k][8c], k<512
    ull* combA = (ull*)(sm + WEIGHT_FLOATS);        // [8 grp][16]
    ull* combB = combA + 128;

    int tid  = threadIdx.x;
    int cb   = blockIdx.x;
    int lane = tid & 31;
    int wid  = tid >> 5;
    int sg   = wid & 7;
    int kh   = wid >> 3;                   // k-half

    for (int idx = tid; idx < 8 * HDIM; idx += 512) {
        int c = idx >> 10;
        int k = idx & 1023;
        Wh0[k * 8 + c] = __ldg(Whh0 + (size_t)(cb * 8 + c) * HDIM + k);
        Wi1[k * 8 + c] = __ldg(Wih1 + (size_t)(cb * 8 + c) * HDIM + k);
        Wh1[k * 8 + c] = __ldg(Whh1 + (size_t)(cb * 8 + c) * HDIM + k);
    }
    for (int idx = tid; idx < 8 * IDIM; idx += 512) {
        int c = idx >> 9;
        int k = idx & 511;
        Wi0[k * 8 + c] = __ldg(Wih0 + (size_t)(cb * 8 + c) * IDIM + k);
    }
    __syncthreads();

    int half = (lane >> 2) & 1;
    int cp_r = 2 * (lane & 1) + ((lane >> 1) & 1);
    int b_r  = 2 * ((lane >> 2) & 1) + ((lane >> 3) & 1);
    int col0 = cb * 8 + 2 * cp_r;
    int gb   = sg * 4 + b_r;

    const unsigned* fpp1 = g_fh1 + sg * 128;
    const unsigned* fpp2 = g_fh2 + sg * 128;
    unsigned* myf1 = g_fh1 + sg * 128 + cb;
    unsigned* myf2 = g_fh2 + sg * 128 + cb;

    float2 b0sum, b1sum;
    b0sum.x = __ldg(bih0 + col0) + __ldg(bhh0 + col0);
    b0sum.y = __ldg(bih0 + col0 + 1) + __ldg(bhh0 + col0 + 1);
    b1sum.x = __ldg(bih1 + col0) + __ldg(bhh1 + col0);
    b1sum.y = __ldg(bih1 + col0 + 1) + __ldg(bhh1 + col0 + 1);

    // per-warp weight bases (k-half offset: 512 rows * 32B = 16384B; x: 8192B)
    const char* wi0A = (const char*)Wi0 + lane * 32 + half * 16 + kh * 8192;
    const char* wi0B = (const char*)Wi0 + lane * 32 + (1 - half) * 16 + kh * 8192;
    const char* wh0A = (const char*)Wh0 + lane * 32 + half * 16 + kh * 16384;
    const char* wh0B = (const char*)Wh0 + lane * 32 + (1 - half) * 16 + kh * 16384;
    const char* wi1A = (const char*)Wi1 + lane * 32 + half * 16 + kh * 16384;
    const char* wi1B = (const char*)Wi1 + lane * 32 + (1 - half) * 16 + kh * 16384;
    const char* wh1A = (const char*)Wh1 + lane * 32 + half * 16 + kh * 16384;
    const char* wh1B = (const char*)Wh1 + lane * 32 + (1 - half) * 16 + kh * 16384;

    ull* cA = combA + sg * 16;
    ull* cB = combB + sg * 16;

    unsigned f1k = 0, f2k = 0;

    #pragma unroll 1
    for (int i = 0; i <= TDIM; i++) {
        int s = i - 1;

        // ---- x-dot half (independent prework) ----
        Accs xa;
        zero_accs(xa);
        if (i < TDIM) {
            const char* xb = (const char*)(xs + (((size_t)i * 8 + sg) << 11))
                             + lane * 16 + kh * 4096;
            dot_into<2>(xa, wi0A, wi0B, xb);
        }

        // ---- polls (cached-min skip) ----
        if (i > 0) {
            if (f1k < (unsigned)i)
                f1k = poll_min(fpp1, (unsigned)i, lane);
            if (s > 0 && f2k < (unsigned)s)
                f2k = poll_min(fpp2, (unsigned)s, lane);
        }

        // ---- dual dot over h1(i-1) k-half ----
        Accs za;
        zero_accs(za);
        if (i > 0) {
            const char* hb = (const char*)&g_hp1[sg][(i - 1) & 3][0]
                             + lane * 16 + kh * 8192;
            dual_dot_into<4>(xa, za, wh0A, wh0B, wi1A, wi1B, hb);
        }

        // ---- combine halves, part A ----
        ull pa = norm_reduce(xa, lane, half);
        if (kh == 1 && lane < 16) cA[lane] = pa;
        barrier_pair(sg);
        if (i < TDIM && kh == 0) {
            add2(pa, cA[lane & 15]);
            float2 u = unpack2(pa);
            float v0 = tanhf(b0sum.x + u.x);
            float v1 = tanhf(b0sum.y + u.y);
            if (lane < 16) {
                float* pb = &g_hp1[sg][i & 3][0];
                pb[(col0 + 0) * 4 + b_r] = v0;
                pb[(col0 + 1) * 4 + b_r] = v1;
            }
            __syncwarp();
            if (lane == 0) {
                asm volatile("st.release.gpu.u32 [%0], %1;"
                             :: "l"(myf1), "r"((unsigned)(i + 1)));
            }
        }

        // ---- h2-dot half, combine, part B ----
        if (i > 0 && s > 0) {
            const char* hb2 = (const char*)&g_hp2[sg][(s - 1) & 3][0]
                              + lane * 16 + kh * 8192;
            dot_into<4>(za, wh1A, wh1B, hb2);
        }
        ull pz = norm_reduce(za, lane, half);
        if (kh == 1 && lane < 16) cB[lane] = pz;
        barrier_pair(sg);
        if (i > 0 && kh == 0) {
            add2(pz, cB[lane & 15]);
            float2 u = unpack2(pz);
            float v0 = tanhf(b1sum.x + u.x);
            float v1 = tanhf(b1sum.y + u.y);
            if (lane < 16) {
                *(float2*)(out + ((size_t)gb * TDIM + s) * HDIM + col0)
                    = make_float2(v0, v1);
                float* pb = &g_hp2[sg][s & 3][0];
                pb[(col0 + 0) * 4 + b_r] = v0;
                pb[(col0 + 1) * 4 + b_r] = v1;
            }
            __syncwarp();
            if (lane == 0) {
                asm volatile("st.release.gpu.u32 [%0], %1;"
                             :: "l"(myf2), "r"((unsigned)(s + 1)));
            }
        }
    }
}

// ---------------- launch ----------------
extern "C" void kernel_launch(void* const* d_in, const int* in_sizes, int n_in,
                              void* d_out, int out_size)
{
    const float* x    = (const float*)d_in[0];
    const float* Wih0 = (const float*)d_in[1];
    const float* Whh0 = (const float*)d_in[2];
    const float* bih0 = (const float*)d_in[3];
    const float* bhh0 = (const float*)d_in[4];
    const float* Wih1 = (const float*)d_in[5];
    const float* Whh1 = (const float*)d_in[6];
    const float* bih1 = (const float*)d_in[7];
    const float* bhh1 = (const float*)d_in[8];
    float* out = (float*)d_out;

    float* xs;
    cudaGetSymbolAddress((void**)&xs, g_xs);

    cudaFuncSetAttribute(recur_fused, cudaFuncAttributeMaxDynamicSharedMemorySize,
                         FU_SMEM_BYTES);

    stage_x<<<TDIM, 256>>>(x);
    recur_fused<<<128, 512, FU_SMEM_BYTES>>>(xs, Whh0, Wih0, Wih1, Whh1,
                                             bih0, bhh0, bih1, bhh1, out);
}

// round 16
// speedup vs baseline: 1.2543x; 1.2543x over previous
#include <cuda_runtime.h>
#include <cuda_bf16.h>
#include <stdint.h>

typedef unsigned long long ull;

// Problem dims
#define BDIM 32
#define TDIM 512
#define IDIM 512
#define HDIM 1024

// ---------------- scratch (static device globals; no allocation) ----------------
__device__ float g_xs[(size_t)TDIM * 8 * IDIM * 4];   // x staged: [t][grp][k][4b]
__device__ float g_hp1[8][4][HDIM * 4];               // h1 ring: [grp][slot][k][4b]
__device__ float g_hp2[8][4][HDIM * 4];               // h2 ring

__device__ unsigned g_fh1[1024];                      // [grp][cb] layer-0 progress
__device__ unsigned g_fh2[1024];                      // layer-1 progress

// ---------------- f32x2 helpers ----------------
__device__ __forceinline__ void ffma2(ull& d, ull a, ull b) {
    asm("fma.rn.f32x2 %0, %1, %2, %0;" : "+l"(d) : "l"(a), "l"(b));
}
__device__ __forceinline__ void add2(ull& d, ull a) {
    asm("add.rn.f32x2 %0, %0, %1;" : "+l"(d) : "l"(a));
}
__device__ __forceinline__ ull splat2(float x) {
    ull r;
    asm("mov.b64 %0, {%1, %1};" : "=l"(r) : "f"(x));
    return r;
}
__device__ __forceinline__ float2 unpack2(ull v) {
    float lo, hi;
    asm("mov.b64 {%0, %1}, %2;" : "=f"(lo), "=f"(hi) : "l"(v));
    return make_float2(lo, hi);
}
__device__ __forceinline__ float4 ldcg_f4(const void* p) {
    float4 v;
    asm volatile("ld.global.cg.v4.f32 {%0,%1,%2,%3}, [%4];"
                 : "=f"(v.x), "=f"(v.y), "=f"(v.z), "=f"(v.w) : "l"(p));
    return v;
}

// ---------------- stage x (+ flag init in CTA 0) ----------------
__global__ __launch_bounds__(256) void stage_x(const float* __restrict__ x) {
    int t = blockIdx.x;
    int tid = threadIdx.x;
    if (blockIdx.x == 0) {
        for (int i = tid; i < 1024; i += 256) {
            g_fh1[i] = 0;
            g_fh2[i] = 0;
        }
    }
    for (int idx = tid; idx < 8 * IDIM; idx += 256) {
        int sg = idx >> 9;
        int k  = idx & 511;
        const float* xb = x + (size_t)t * IDIM + k;
        float4 v;
        v.x = xb[(size_t)(sg * 4 + 0) * TDIM * IDIM];
        v.y = xb[(size_t)(sg * 4 + 1) * TDIM * IDIM];
        v.z = xb[(size_t)(sg * 4 + 2) * TDIM * IDIM];
        v.w = xb[(size_t)(sg * 4 + 3) * TDIM * IDIM];
        *(float4*)(g_xs + (((size_t)t * 8 + sg) << 11) + k * 4) = v;
    }
}

// ---------------- acc structure and helpers ----------------
struct Accs { ull v[16]; };   // [A0 b0..3 | A1 b0..3 | B0 b0..3 | B1 b0..3]

__device__ __forceinline__ void zero_accs(Accs& a) {
    #pragma unroll
    for (int i = 0; i < 16; i++) a.v[i] = 0ull;
}

__device__ __forceinline__ void acc_step(Accs& a, ulonglong2 w1, ulonglong2 w2,
                                         float4 h) {
    ull s0 = splat2(h.x), s1 = splat2(h.y);
    ull s2 = splat2(h.z), s3 = splat2(h.w);
    ffma2(a.v[0],  s0, w1.x); ffma2(a.v[4],  s0, w1.y);
    ffma2(a.v[8],  s0, w2.x); ffma2(a.v[12], s0, w2.y);
    ffma2(a.v[1],  s1, w1.x); ffma2(a.v[5],  s1, w1.y);
    ffma2(a.v[9],  s1, w2.x); ffma2(a.v[13], s1, w2.y);
    ffma2(a.v[2],  s2, w1.x); ffma2(a.v[6],  s2, w1.y);
    ffma2(a.v[10], s2, w2.x); ffma2(a.v[14], s2, w2.y);
    ffma2(a.v[3],  s3, w1.x); ffma2(a.v[7],  s3, w1.y);
    ffma2(a.v[11], s3, w2.x); ffma2(a.v[15], s3, w2.y);
}

// single-weight dot over CHUNKS*4*32 k — depth-4 circular prefetch
template<int CHUNKS>
__device__ __forceinline__ void dot_into(Accs& ac,
                                         const char* __restrict__ wA,
                                         const char* __restrict__ wB,
                                         const char* __restrict__ hbase) {
    float4 hbuf[4][4];
    constexpr int PRE = (CHUNKS < 4) ? CHUNKS : 4;
    #pragma unroll
    for (int c = 0; c < PRE; c++)
        #pragma unroll
        for (int j = 0; j < 4; j++)
            hbuf[c][j] = ldcg_f4(hbase + (c * 4 + j) * 512);

    #pragma unroll
    for (int c = 0; c < CHUNKS; c++) {
        int slot = c & 3;
        #pragma unroll
        for (int j = 0; j < 4; j++) {
            int koff = (c * 4 + j) * 1024;
            ulonglong2 w1 = *(const ulonglong2*)(wA + koff);
            ulonglong2 w2 = *(const ulonglong2*)(wB + koff);
            acc_step(ac, w1, w2, hbuf[slot][j]);
        }
        if (c + 4 < CHUNKS) {
            #pragma unroll
            for (int j = 0; j < 4; j++)
                hbuf[slot][j] = ldcg_f4(hbase + ((c + 4) * 4 + j) * 512);
        }
    }
}

// dual-weight dot: read h once, accumulate into two acc sets — depth-4 prefetch
__device__ __forceinline__ void dual_dot_into(Accs& xa, Accs& za,
                                              const char* __restrict__ waA,
                                              const char* __restrict__ waB,
                                              const char* __restrict__ wzA,
                                              const char* __restrict__ wzB,
                                              const char* __restrict__ hbase) {
    float4 hbuf[4][4];
    #pragma unroll
    for (int c = 0; c < 4; c++)
        #pragma unroll
        for (int j = 0; j < 4; j++)
            hbuf[c][j] = ldcg_f4(hbase + (c * 4 + j) * 512);

    #pragma unroll
    for (int c = 0; c < 8; c++) {
        int slot = c & 3;
        #pragma unroll
        for (int j = 0; j < 4; j++) {
            int koff = (c * 4 + j) * 1024;
            float4 h = hbuf[slot][j];
            ulonglong2 w1 = *(const ulonglong2*)(waA + koff);
            ulonglong2 w2 = *(const ulonglong2*)(waB + koff);
            acc_step(xa, w1, w2, h);
            ulonglong2 z1 = *(const ulonglong2*)(wzA + koff);
            ulonglong2 z2 = *(const ulonglong2*)(wzB + koff);
            acc_step(za, z1, z2, h);
        }
        if (c + 4 < 8) {
            #pragma unroll
            for (int j = 0; j < 4; j++)
                hbuf[slot][j] = ldcg_f4(hbase + ((c + 4) * 4 + j) * 512);
        }
    }
}

// butterfly reduction of 16 acc-pairs across 32 lanes -> 1 pair per lane
__device__ __forceinline__ ull reduce16(ull* a, int lane) {
    #pragma unroll
    for (int i = 0; i < 16; i++) {
        ull r = __shfl_xor_sync(0xffffffffu, a[i], 16);
        add2(a[i], r);
    }
    {
        int bit = lane & 1;
        #pragma unroll
        for (int i = 0; i < 8; i++) {
            ull snd = bit ? a[i] : a[i + 8];
            ull rcv = __shfl_xor_sync(0xffffffffu, snd, 1);
            a[i] = bit ? a[i + 8] : a[i];
            add2(a[i], rcv);
        }
    }
    {
        int bit = (lane >> 1) & 1;
        #pragma unroll
        for (int i = 0; i < 4; i++) {
            ull snd = bit ? a[i] : a[i + 4];
            ull rcv = __shfl_xor_sync(0xffffffffu, snd, 2);
            a[i] = bit ? a[i + 4] : a[i];
            add2(a[i], rcv);
        }
    }
    {
        int bit = (lane >> 2) & 1;
        #pragma unroll
        for (int i = 0; i < 2; i++) {
            ull snd = bit ? a[i] : a[i + 2];
            ull rcv = __shfl_xor_sync(0xffffffffu, snd, 4);
            a[i] = bit ? a[i + 2] : a[i];
            add2(a[i], rcv);
        }
    }
    {
        int bit = (lane >> 3) & 1;
        ull snd = bit ? a[0] : a[1];
        ull rcv = __shfl_xor_sync(0xffffffffu, snd, 8);
        a[0] = bit ? a[1] : a[0];
        add2(a[0], rcv);
    }
    return a[0];
}

__device__ __forceinline__ ull norm_reduce(const Accs& ac, int lane, int half) {
    ull a[16];
    if (half == 0) {
        #pragma unroll
        for (int i = 0; i < 16; i++) a[i] = ac.v[i];
    } else {
        #pragma unroll
        for (int i = 0; i < 8; i++) {
            a[i]     = ac.v[i + 8];
            a[i + 8] = ac.v[i];
        }
    }
    return reduce16(a, lane);
}

// poll all 128 flags of a group until min >= tt; returns the observed min
// (monotonic flags: caller caches it to skip future polls entirely)
__device__ __forceinline__ unsigned poll_min(const unsigned* __restrict__ fpp,
                                             unsigned tt, int lane) {
    unsigned m;
    for (;;) {
        unsigned f0, f1, f2, f3;
        asm volatile("ld.acquire.gpu.u32 %0, [%1];" : "=r"(f0) : "l"(fpp + lane));
        asm volatile("ld.acquire.gpu.u32 %0, [%1];" : "=r"(f1) : "l"(fpp + lane + 32));
        asm volatile("ld.acquire.gpu.u32 %0, [%1];" : "=r"(f2) : "l"(fpp + lane + 64));
        asm volatile("ld.acquire.gpu.u32 %0, [%1];" : "=r"(f3) : "l"(fpp + lane + 96));
        unsigned mn = min(min(f0, f1), min(f2, f3));
        m = __reduce_min_sync(0xffffffffu, mn);
        if (m >= tt) break;
    }
    return m;
}

// ---------------- fully fused: xw0 GEMM + 2-layer pipelined recurrence ----------------
// smem: Wh0 (32KB) + Wi1 (32KB) + Wh1 (32KB) + Wi0 (16KB) = 112KB
#define FU_SMEM_BYTES ((3 * 8 * HDIM + 8 * IDIM) * 4)

__global__ __launch_bounds__(256, 1) void recur_fused(
    const float* __restrict__ xs,
    const float* __restrict__ Whh0,
    const float* __restrict__ Wih0,
    const float* __restrict__ Wih1,
    const float* __restrict__ Whh1,
    const float* __restrict__ bih0,
    const float* __restrict__ bhh0,
    const float* __restrict__ bih1,
    const float* __restrict__ bhh1,
    float* __restrict__ out)
{
    extern __shared__ __align__(16) float sm[];
    float* Wh0 = sm;                       // [k][8c], k<1024
    float* Wi1 = sm + 8 * HDIM;
    float* Wh1 = sm + 16 * HDIM;
    float* Wi0 = sm + 24 * HDIM;           // [k][8c], k<512

    int tid  = threadIdx.x;
    int cb   = blockIdx.x;
    int lane = tid & 31;
    int sg   = tid >> 5;

    for (int idx = tid; idx < 8 * HDIM; idx += 256) {
        int c = idx >> 10;
        int k = idx & 1023;
        Wh0[k * 8 + c] = __ldg(Whh0 + (size_t)(cb * 8 + c) * HDIM + k);
        Wi1[k * 8 + c] = __ldg(Wih1 + (size_t)(cb * 8 + c) * HDIM + k);
        Wh1[k * 8 + c] = __ldg(Whh1 + (size_t)(cb * 8 + c) * HDIM + k);
    }
    for (int idx = tid; idx < 8 * IDIM; idx += 256) {
        int c = idx >> 9;
        int k = idx & 511;
        Wi0[k * 8 + c] = __ldg(Wih0 + (size_t)(cb * 8 + c) * IDIM + k);
    }
    __syncthreads();

    int half = (lane >> 2) & 1;
    int cp_r = 2 * (lane & 1) + ((lane >> 1) & 1);
    int b_r  = 2 * ((lane >> 2) & 1) + ((lane >> 3) & 1);
    int col0 = cb * 8 + 2 * cp_r;
    int gb   = sg * 4 + b_r;

    const unsigned* fpp1 = g_fh1 + sg * 128;
    const unsigned* fpp2 = g_fh2 + sg * 128;
    unsigned* myf1 = g_fh1 + sg * 128 + cb;
    unsigned* myf2 = g_fh2 + sg * 128 + cb;

    float2 b0sum, b1sum;
    b0sum.x = __ldg(bih0 + col0) + __ldg(bhh0 + col0);
    b0sum.y = __ldg(bih0 + col0 + 1) + __ldg(bhh0 + col0 + 1);
    b1sum.x = __ldg(bih1 + col0) + __ldg(bhh1 + col0);
    b1sum.y = __ldg(bih1 + col0 + 1) + __ldg(bhh1 + col0 + 1);

    const char* wi0A = (const char*)Wi0 + lane * 32 + half * 16;
    const char* wi0B = (const char*)Wi0 + lane * 32 + (1 - half) * 16;
    const char* wh0A = (const char*)Wh0 + lane * 32 + half * 16;
    const char* wh0B = (const char*)Wh0 + lane * 32 + (1 - half) * 16;
    const char* wi1A = (const char*)Wi1 + lane * 32 + half * 16;
    const char* wi1B = (const char*)Wi1 + lane * 32 + (1 - half) * 16;
    const char* wh1A = (const char*)Wh1 + lane * 32 + half * 16;
    const char* wh1B = (const char*)Wh1 + lane * 32 + (1 - half) * 16;

    unsigned f1k = 0, f2k = 0;   // cached lower bounds on group flag minima

    #pragma unroll 1
    for (int i = 0; i <= TDIM; i++) {
        int s = i - 1;

        // ---- x-dot: seed a-accs with Wih0 . x(i)  (all loads issued up front) ----
        Accs xa;
        zero_accs(xa);
        if (i < TDIM) {
            const char* xb = (const char*)(xs + (((size_t)i * 8 + sg) << 11))
                             + lane * 16;
            dot_into<4>(xa, wi0A, wi0B, xb);
        }

        // ---- polls (skipped when cached min already covers the step) ----
        if (i > 0) {
            if (f1k < (unsigned)i)
                f1k = poll_min(fpp1, (unsigned)i, lane);
            if (s > 0 && f2k < (unsigned)s)
                f2k = poll_min(fpp2, (unsigned)s, lane);
        }

        // ---- dual dot over h1(i-1): xa += Wh0.h1 ; za = Wi1.h1 ----
        Accs za;
        zero_accs(za);
        if (i > 0) {
            const char* hb = (const char*)&g_hp1[sg][(i - 1) & 3][0] + lane * 16;
            dual_dot_into(xa, za, wh0A, wh0B, wi1A, wi1B, hb);
        }

        // ---- part A: h1(i) = tanh(b0 + Wih0.x(i) + Whh0.h1(i-1)) ----
        if (i < TDIM) {
            float2 u = unpack2(norm_reduce(xa, lane, half));
            float v0 = tanhf(b0sum.x + u.x);
            float v1 = tanhf(b0sum.y + u.y);
            if (lane < 16) {
                float* pb = &g_hp1[sg][i & 3][0];
                pb[(col0 + 0) * 4 + b_r] = v0;
                pb[(col0 + 1) * 4 + b_r] = v1;
            }
            __syncwarp();
            if (lane == 0) {
                asm volatile("st.release.gpu.u32 [%0], %1;"
                             :: "l"(myf1), "r"((unsigned)(i + 1)));
            }
        }

        // ---- part B: h2(s) = tanh(b1 + Wih1.h1(s) + Whh1.h2(s-1)) ----
        if (i > 0) {
            if (s > 0) {
                const char* hb2 = (const char*)&g_hp2[sg][(s - 1) & 3][0]
                                  + lane * 16;
                dot_into<8>(za, wh1A, wh1B, hb2);   // folded: single reduce
            }
            float2 u = unpack2(norm_reduce(za, lane, half));
            float v0 = tanhf(b1sum.x + u.x);
            float v1 = tanhf(b1sum.y + u.y);

            if (lane < 16) {
                *(float2*)(out + ((size_t)gb * TDIM + s) * HDIM + col0)
                    = make_float2(v0, v1);
                float* pb = &g_hp2[sg][s & 3][0];
                pb[(col0 + 0) * 4 + b_r] = v0;
                pb[(col0 + 1) * 4 + b_r] = v1;
            }
            __syncwarp();
            if (lane == 0) {
                asm volatile("st.release.gpu.u32 [%0], %1;"
                             :: "l"(myf2), "r"((unsigned)(s + 1)));
            }
        }
    }
}

// ---------------- launch ----------------
extern "C" void kernel_launch(void* const* d_in, const int* in_sizes, int n_in,
                              void* d_out, int out_size)
{
    const float* x    = (const float*)d_in[0];
    const float* Wih0 = (const float*)d_in[1];
    const float* Whh0 = (const float*)d_in[2];
    const float* bih0 = (const float*)d_in[3];
    const float* bhh0 = (const float*)d_in[4];
    const float* Wih1 = (const float*)d_in[5];
    const float* Whh1 = (const float*)d_in[6];
    const float* bih1 = (const float*)d_in[7];
    const float* bhh1 = (const float*)d_in[8];
    float* out = (float*)d_out;

    float* xs;
    cudaGetSymbolAddress((void**)&xs, g_xs);

    cudaFuncSetAttribute(recur_fused, cudaFuncAttributeMaxDynamicSharedMemorySize,
                         FU_SMEM_BYTES);

    stage_x<<<TDIM, 256>>>(x);
    recur_fused<<<128, 256, FU_SMEM_BYTES>>>(xs, Whh0, Wih0, Wih1, Whh1,
                                             bih0, bhh0, bih1, bhh1, out);
}

// round 17
// speedup vs baseline: 1.2631x; 1.0071x over previous
#include <cuda_runtime.h>
#include <cuda_bf16.h>
#include <stdint.h>

typedef unsigned long long ull;

// Problem dims
#define BDIM 32
#define TDIM 512
#define IDIM 512
#define HDIM 1024

// ---------------- scratch (static device globals; no allocation) ----------------
__device__ float g_xs[(size_t)TDIM * 8 * IDIM * 4];   // x staged: [t][grp][k][4b]
__device__ float g_hp1[8][4][HDIM * 4];               // h1 ring: [grp][slot][k][4b]
__device__ float g_hp2[8][4][HDIM * 4];               // h2 ring

__device__ unsigned g_fh1[1024];                      // [grp][cb] layer-0 progress
__device__ unsigned g_fh2[1024];                      // layer-1 progress

// ---------------- f32x2 helpers ----------------
__device__ __forceinline__ void ffma2(ull& d, ull a, ull b) {
    asm("fma.rn.f32x2 %0, %1, %2, %0;" : "+l"(d) : "l"(a), "l"(b));
}
__device__ __forceinline__ void add2(ull& d, ull a) {
    asm("add.rn.f32x2 %0, %0, %1;" : "+l"(d) : "l"(a));
}
__device__ __forceinline__ ull splat2(float x) {
    ull r;
    asm("mov.b64 %0, {%1, %1};" : "=l"(r) : "f"(x));
    return r;
}
__device__ __forceinline__ float2 unpack2(ull v) {
    float lo, hi;
    asm("mov.b64 {%0, %1}, %2;" : "=f"(lo), "=f"(hi) : "l"(v));
    return make_float2(lo, hi);
}
__device__ __forceinline__ float4 ldcg_f4(const void* p) {
    float4 v;
    asm volatile("ld.global.cg.v4.f32 {%0,%1,%2,%3}, [%4];"
                 : "=f"(v.x), "=f"(v.y), "=f"(v.z), "=f"(v.w) : "l"(p));
    return v;
}

// ---------------- stage x (+ flag init in CTA 0) ----------------
__global__ __launch_bounds__(256) void stage_x(const float* __restrict__ x) {
    int t = blockIdx.x;
    int tid = threadIdx.x;
    if (blockIdx.x == 0) {
        for (int i = tid; i < 1024; i += 256) {
            g_fh1[i] = 0;
            g_fh2[i] = 0;
        }
    }
    for (int idx = tid; idx < 8 * IDIM; idx += 256) {
        int sg = idx >> 9;
        int k  = idx & 511;
        const float* xb = x + (size_t)t * IDIM + k;
        float4 v;
        v.x = xb[(size_t)(sg * 4 + 0) * TDIM * IDIM];
        v.y = xb[(size_t)(sg * 4 + 1) * TDIM * IDIM];
        v.z = xb[(size_t)(sg * 4 + 2) * TDIM * IDIM];
        v.w = xb[(size_t)(sg * 4 + 3) * TDIM * IDIM];
        *(float4*)(g_xs + (((size_t)t * 8 + sg) << 11) + k * 4) = v;
    }
}

// ---------------- acc structure and helpers ----------------
struct Accs { ull v[16]; };   // [A0 b0..3 | A1 b0..3 | B0 b0..3 | B1 b0..3]

__device__ __forceinline__ void zero_accs(Accs& a) {
    #pragma unroll
    for (int i = 0; i < 16; i++) a.v[i] = 0ull;
}

__device__ __forceinline__ void acc_step(Accs& a, ulonglong2 w1, ulonglong2 w2,
                                         float4 h) {
    ull s0 = splat2(h.x), s1 = splat2(h.y);
    ull s2 = splat2(h.z), s3 = splat2(h.w);
    ffma2(a.v[0],  s0, w1.x); ffma2(a.v[4],  s0, w1.y);
    ffma2(a.v[8],  s0, w2.x); ffma2(a.v[12], s0, w2.y);
    ffma2(a.v[1],  s1, w1.x); ffma2(a.v[5],  s1, w1.y);
    ffma2(a.v[9],  s1, w2.x); ffma2(a.v[13], s1, w2.y);
    ffma2(a.v[2],  s2, w1.x); ffma2(a.v[6],  s2, w1.y);
    ffma2(a.v[10], s2, w2.x); ffma2(a.v[14], s2, w2.y);
    ffma2(a.v[3],  s3, w1.x); ffma2(a.v[7],  s3, w1.y);
    ffma2(a.v[11], s3, w2.x); ffma2(a.v[15], s3, w2.y);
}

// single-weight dot over CHUNKS*4*32 k — depth-4 circular prefetch
template<int CHUNKS>
__device__ __forceinline__ void dot_into(Accs& ac,
                                         const char* __restrict__ wA,
                                         const char* __restrict__ wB,
                                         const char* __restrict__ hbase) {
    float4 hbuf[4][4];
    constexpr int PRE = (CHUNKS < 4) ? CHUNKS : 4;
    #pragma unroll
    for (int c = 0; c < PRE; c++)
        #pragma unroll
        for (int j = 0; j < 4; j++)
            hbuf[c][j] = ldcg_f4(hbase + (c * 4 + j) * 512);

    #pragma unroll
    for (int c = 0; c < CHUNKS; c++) {
        int slot = c & 3;
        #pragma unroll
        for (int j = 0; j < 4; j++) {
            int koff = (c * 4 + j) * 1024;
            ulonglong2 w1 = *(const ulonglong2*)(wA + koff);
            ulonglong2 w2 = *(const ulonglong2*)(wB + koff);
            acc_step(ac, w1, w2, hbuf[slot][j]);
        }
        if (c + 4 < CHUNKS) {
            #pragma unroll
            for (int j = 0; j < 4; j++)
                hbuf[slot][j] = ldcg_f4(hbase + ((c + 4) * 4 + j) * 512);
        }
    }
}

// dual-weight dot: read h once, accumulate into two acc sets — depth-4 prefetch
__device__ __forceinline__ void dual_dot_into(Accs& xa, Accs& za,
                                              const char* __restrict__ waA,
                                              const char* __restrict__ waB,
                                              const char* __restrict__ wzA,
                                              const char* __restrict__ wzB,
                                              const char* __restrict__ hbase) {
    float4 hbuf[4][4];
    #pragma unroll
    for (int c = 0; c < 4; c++)
        #pragma unroll
        for (int j = 0; j < 4; j++)
            hbuf[c][j] = ldcg_f4(hbase + (c * 4 + j) * 512);

    #pragma unroll
    for (int c = 0; c < 8; c++) {
        int slot = c & 3;
        #pragma unroll
        for (int j = 0; j < 4; j++) {
            int koff = (c * 4 + j) * 1024;
            float4 h = hbuf[slot][j];
            ulonglong2 w1 = *(const ulonglong2*)(waA + koff);
            ulonglong2 w2 = *(const ulonglong2*)(waB + koff);
            acc_step(xa, w1, w2, h);
            ulonglong2 z1 = *(const ulonglong2*)(wzA + koff);
            ulonglong2 z2 = *(const ulonglong2*)(wzB + koff);
            acc_step(za, z1, z2, h);
        }
        if (c + 4 < 8) {
            #pragma unroll
            for (int j = 0; j < 4; j++)
                hbuf[slot][j] = ldcg_f4(hbase + ((c + 4) * 4 + j) * 512);
        }
    }
}

// butterfly reduction of 16 acc-pairs across 32 lanes -> 1 pair per lane
__device__ __forceinline__ ull reduce16(ull* a, int lane) {
    #pragma unroll
    for (int i = 0; i < 16; i++) {
        ull r = __shfl_xor_sync(0xffffffffu, a[i], 16);
        add2(a[i], r);
    }
    {
        int bit = lane & 1;
        #pragma unroll
        for (int i = 0; i < 8; i++) {
            ull snd = bit ? a[i] : a[i + 8];
            ull rcv = __shfl_xor_sync(0xffffffffu, snd, 1);
            a[i] = bit ? a[i + 8] : a[i];
            add2(a[i], rcv);
        }
    }
    {
        int bit = (lane >> 1) & 1;
        #pragma unroll
        for (int i = 0; i < 4; i++) {
            ull snd = bit ? a[i] : a[i + 4];
            ull rcv = __shfl_xor_sync(0xffffffffu, snd, 2);
            a[i] = bit ? a[i + 4] : a[i];
            add2(a[i], rcv);
        }
    }
    {
        int bit = (lane >> 2) & 1;
        #pragma unroll
        for (int i = 0; i < 2; i++) {
            ull snd = bit ? a[i] : a[i + 2];
            ull rcv = __shfl_xor_sync(0xffffffffu, snd, 4);
            a[i] = bit ? a[i + 2] : a[i];
            add2(a[i], rcv);
        }
    }
    {
        int bit = (lane >> 3) & 1;
        ull snd = bit ? a[0] : a[1];
        ull rcv = __shfl_xor_sync(0xffffffffu, snd, 8);
        a[0] = bit ? a[1] : a[0];
        add2(a[0], rcv);
    }
    return a[0];
}

__device__ __forceinline__ ull norm_reduce(const Accs& ac, int lane, int half) {
    ull a[16];
    if (half == 0) {
        #pragma unroll
        for (int i = 0; i < 16; i++) a[i] = ac.v[i];
    } else {
        #pragma unroll
        for (int i = 0; i < 8; i++) {
            a[i]     = ac.v[i + 8];
            a[i + 8] = ac.v[i];
        }
    }
    return reduce16(a, lane);
}

// poll all 128 flags of a group until min >= tt; returns the observed min
// (monotonic flags: caller caches it to skip future polls entirely)
__device__ __forceinline__ unsigned poll_min(const unsigned* __restrict__ fpp,
                                             unsigned tt, int lane) {
    unsigned m;
    for (;;) {
        unsigned f0, f1, f2, f3;
        asm volatile("ld.acquire.gpu.u32 %0, [%1];" : "=r"(f0) : "l"(fpp + lane));
        asm volatile("ld.acquire.gpu.u32 %0, [%1];" : "=r"(f1) : "l"(fpp + lane + 32));
        asm volatile("ld.acquire.gpu.u32 %0, [%1];" : "=r"(f2) : "l"(fpp + lane + 64));
        asm volatile("ld.acquire.gpu.u32 %0, [%1];" : "=r"(f3) : "l"(fpp + lane + 96));
        unsigned mn = min(min(f0, f1), min(f2, f3));
        m = __reduce_min_sync(0xffffffffu, mn);
        if (m >= tt) break;
    }
    return m;
}

// ---------------- fully fused: xw0 GEMM + 2-layer pipelined recurrence ----------------
// smem: Wh0 (32KB) + Wi1 (32KB) + Wh1 (32KB) + Wi0 (16KB) = 112KB
#define FU_SMEM_BYTES ((3 * 8 * HDIM + 8 * IDIM) * 4)

__global__ __launch_bounds__(256, 1) void recur_fused(
    const float* __restrict__ xs,
    const float* __restrict__ Whh0,
    const float* __restrict__ Wih0,
    const float* __restrict__ Wih1,
    const float* __restrict__ Whh1,
    const float* __restrict__ bih0,
    const float* __restrict__ bhh0,
    const float* __restrict__ bih1,
    const float* __restrict__ bhh1,
    float* __restrict__ out)
{
    extern __shared__ __align__(16) float sm[];
    float* Wh0 = sm;                       // [k][8c], k<1024
    float* Wi1 = sm + 8 * HDIM;
    float* Wh1 = sm + 16 * HDIM;
    float* Wi0 = sm + 24 * HDIM;           // [k][8c], k<512

    int tid  = threadIdx.x;
    int cb   = blockIdx.x;
    int lane = tid & 31;
    int sg   = tid >> 5;

    for (int idx = tid; idx < 8 * HDIM; idx += 256) {
        int c = idx >> 10;
        int k = idx & 1023;
        Wh0[k * 8 + c] = __ldg(Whh0 + (size_t)(cb * 8 + c) * HDIM + k);
        Wi1[k * 8 + c] = __ldg(Wih1 + (size_t)(cb * 8 + c) * HDIM + k);
        Wh1[k * 8 + c] = __ldg(Whh1 + (size_t)(cb * 8 + c) * HDIM + k);
    }
    for (int idx = tid; idx < 8 * IDIM; idx += 256) {
        int c = idx >> 9;
        int k = idx & 511;
        Wi0[k * 8 + c] = __ldg(Wih0 + (size_t)(cb * 8 + c) * IDIM + k);
    }
    __syncthreads();

    // ---- phase stagger: decouple the 8 independent group chains so that
    // SMSP-mates (warps sg and sg+4) run ~half a step out of phase; their
    // FFMA2 bursts then fill each other's poll/load/reduce latency windows.
    // One-time delay; no CTA-wide syncs after this point, so offsets persist.
    {
        long long t0 = clock64();
        long long target = t0 + (long long)sg * 2000;
        while (clock64() < target) { }
    }

    int half = (lane >> 2) & 1;
    int cp_r = 2 * (lane & 1) + ((lane >> 1) & 1);
    int b_r  = 2 * ((lane >> 2) & 1) + ((lane >> 3) & 1);
    int col0 = cb * 8 + 2 * cp_r;
    int gb   = sg * 4 + b_r;

    const unsigned* fpp1 = g_fh1 + sg * 128;
    const unsigned* fpp2 = g_fh2 + sg * 128;
    unsigned* myf1 = g_fh1 + sg * 128 + cb;
    unsigned* myf2 = g_fh2 + sg * 128 + cb;

    float2 b0sum, b1sum;
    b0sum.x = __ldg(bih0 + col0) + __ldg(bhh0 + col0);
    b0sum.y = __ldg(bih0 + col0 + 1) + __ldg(bhh0 + col0 + 1);
    b1sum.x = __ldg(bih1 + col0) + __ldg(bhh1 + col0);
    b1sum.y = __ldg(bih1 + col0 + 1) + __ldg(bhh1 + col0 + 1);

    const char* wi0A = (const char*)Wi0 + lane * 32 + half * 16;
    const char* wi0B = (const char*)Wi0 + lane * 32 + (1 - half) * 16;
    const char* wh0A = (const char*)Wh0 + lane * 32 + half * 16;
    const char* wh0B = (const char*)Wh0 + lane * 32 + (1 - half) * 16;
    const char* wi1A = (const char*)Wi1 + lane * 32 + half * 16;
    const char* wi1B = (const char*)Wi1 + lane * 32 + (1 - half) * 16;
    const char* wh1A = (const char*)Wh1 + lane * 32 + half * 16;
    const char* wh1B = (const char*)Wh1 + lane * 32 + (1 - half) * 16;

    unsigned f1k = 0, f2k = 0;   // cached lower bounds on group flag minima

    #pragma unroll 1
    for (int i = 0; i <= TDIM; i++) {
        int s = i - 1;

        // ---- x-dot: seed a-accs with Wih0 . x(i) ----
        Accs xa;
        zero_accs(xa);
        if (i < TDIM) {
            const char* xb = (const char*)(xs + (((size_t)i * 8 + sg) << 11))
                             + lane * 16;
            dot_into<4>(xa, wi0A, wi0B, xb);
        }

        // ---- polls (skipped when cached min already covers the step) ----
        if (i > 0) {
            if (f1k < (unsigned)i)
                f1k = poll_min(fpp1, (unsigned)i, lane);
            if (s > 0 && f2k < (unsigned)s)
                f2k = poll_min(fpp2, (unsigned)s, lane);
        }

        // ---- dual dot over h1(i-1): xa += Wh0.h1 ; za = Wi1.h1 ----
        Accs za;
        zero_accs(za);
        if (i > 0) {
            const char* hb = (const char*)&g_hp1[sg][(i - 1) & 3][0] + lane * 16;
            dual_dot_into(xa, za, wh0A, wh0B, wi1A, wi1B, hb);
        }

        // ---- part A: h1(i) = tanh(b0 + Wih0.x(i) + Whh0.h1(i-1)) ----
        if (i < TDIM) {
            float2 u = unpack2(norm_reduce(xa, lane, half));
            float v0 = tanhf(b0sum.x + u.x);
            float v1 = tanhf(b0sum.y + u.y);
            if (lane < 16) {
                float* pb = &g_hp1[sg][i & 3][0];
                pb[(col0 + 0) * 4 + b_r] = v0;
                pb[(col0 + 1) * 4 + b_r] = v1;
            }
            __syncwarp();
            if (lane == 0) {
                asm volatile("st.release.gpu.u32 [%0], %1;"
                             :: "l"(myf1), "r"((unsigned)(i + 1)));
            }
        }

        // ---- part B: h2(s) = tanh(b1 + Wih1.h1(s) + Whh1.h2(s-1)) ----
        if (i > 0) {
            if (s > 0) {
                const char* hb2 = (const char*)&g_hp2[sg][(s - 1) & 3][0]
                                  + lane * 16;
                dot_into<8>(za, wh1A, wh1B, hb2);   // folded: single reduce
            }
            float2 u = unpack2(norm_reduce(za, lane, half));
            float v0 = tanhf(b1sum.x + u.x);
            float v1 = tanhf(b1sum.y + u.y);

            if (lane < 16) {
                *(float2*)(out + ((size_t)gb * TDIM + s) * HDIM + col0)
                    = make_float2(v0, v1);
                float* pb = &g_hp2[sg][s & 3][0];
                pb[(col0 + 0) * 4 + b_r] = v0;
                pb[(col0 + 1) * 4 + b_r] = v1;
            }
            __syncwarp();
            if (lane == 0) {
                asm volatile("st.release.gpu.u32 [%0], %1;"
                             :: "l"(myf2), "r"((unsigned)(s + 1)));
            }
        }
    }
}

// ---------------- launch ----------------
extern "C" void kernel_launch(void* const* d_in, const int* in_sizes, int n_in,
                              void* d_out, int out_size)
{
    const float* x    = (const float*)d_in[0];
    const float* Wih0 = (const float*)d_in[1];
    const float* Whh0 = (const float*)d_in[2];
    const float* bih0 = (const float*)d_in[3];
    const float* bhh0 = (const float*)d_in[4];
    const float* Wih1 = (const float*)d_in[5];
    const float* Whh1 = (const float*)d_in[6];
    const float* bih1 = (const float*)d_in[7];
    const float* bhh1 = (const float*)d_in[8];
    float* out = (float*)d_out;

    float* xs;
    cudaGetSymbolAddress((void**)&xs, g_xs);

    cudaFuncSetAttribute(recur_fused, cudaFuncAttributeMaxDynamicSharedMemorySize,
                         FU_SMEM_BYTES);

    stage_x<<<TDIM, 256>>>(x);
    recur_fused<<<128, 256, FU_SMEM_BYTES>>>(xs, Whh0, Wih0, Wih1, Whh1,
                                             bih0, bhh0, bih1, bhh1, out);
}